// round 7
// baseline (speedup 1.0000x reference)
#include <cuda_runtime.h>

// WindowAttention fused kernel (fp32, f32x2-packed FFMA), one CTA per window.
//
// Inputs (metadata order):
//  0 x            (8192, 49, 384) f32
//  1 mask         (64, 49, 49)    f32
//  2 rel_pos_table(169, 12)       f32
//  3 qkv_w        (1152, 384)     f32
//  4 qkv_b        (1152,)         f32
//  5 proj_w       (384, 384)      f32
//  6 proj_b       (384,)          f32
//  7 rel_pos_index(49, 49)        i32
// out (8192, 49, 384) f32

#define NTOK   49
#define NH     12
#define HDM    32
#define DIMM   384
#define NWIN   64
#define SCALE  0.17677669529663687f   // 1/sqrt(32)

#define XSTR 388   // x / attn-out row stride (pad vs 384 for banks, %4==0 for vec4)
#define WSTR 36    // weight tile row stride (conflict-free LDS.128 across lanes)
#define QSTR 33    // q/k/v head-tile row stride (conflict-free scalar column reads)
#define PSTR 52    // softmax probs row stride

// shared memory layout (float offsets)
#define OFF_XS 0                  // 49*388 = 19012
#define OFF_OS 19012              // 49*388 = 19012
#define OFF_WS 38024              // 96*36  = 3456
#define OFF_QS 41480              // 49*33  = 1617
#define OFF_KS 43097              // 1617
#define OFF_VS 44714              // 1617
#define OFF_PS 46331              // 49*52  = 2548
#define OFF_TB 48879              // 169*12 = 2028
#define OFF_MS 50907              // 2401
#define OFF_IX 53308              // 2401 ints
#define SMEM_FLOATS 55709         // 222,836 bytes

typedef unsigned long long u64;

// packed dual-fp32 FMA: d.lo += a.lo*b.lo, d.hi += a.hi*b.hi  (sm_100+ f32x2 pipe)
__device__ __forceinline__ void fma2(u64& d, u64 a, u64 b) {
    asm("fma.rn.f32x2 %0, %1, %2, %3;" : "=l"(d) : "l"(a), "l"(b), "l"(d));
}
__device__ __forceinline__ float unpack_add(u64 v) {
    float lo, hi;
    asm("mov.b64 {%0, %1}, %2;" : "=f"(lo), "=f"(hi) : "l"(v));
    return lo + hi;
}

// C[49][96] = A[49][384](smem, stride XSTR) @ W[96][384]^T  (W from gmem/L2,
// staged through a 96x32 smem tile per K-chunk).
// Thread map: warp w owns rows {w+8j, j=0..6} (j==6 only for warp 0, row 48);
// lane owns cols {lane, lane+32, lane+64}. Accumulation in packed f32x2 pairs.
template<bool IS_QKV>
__device__ __forceinline__ void gemm96(const float* __restrict__ A,
                                       const float* __restrict__ Wg,
                                       int hp,           // head (qkv) or col-tile base (proj)
                                       float* __restrict__ WS,
                                       float fin[7][3],
                                       int tid, int lane, int warp)
{
    u64 acc[7][3];
#pragma unroll
    for (int j = 0; j < 7; j++)
#pragma unroll
        for (int c = 0; c < 3; c++) acc[j][c] = 0ull;

    for (int kk = 0; kk < DIMM; kk += 32) {
        __syncthreads();   // protect WS (and first-call smem init ordering)
        // stage W tile: 96 rows x 32 k (8 float4 per row), coalesced
        for (int i = tid; i < 96 * 8; i += 256) {
            int rw = i >> 3, q4 = i & 7;
            int orow = IS_QKV ? ((rw >> 5) * 384 + hp * HDM + (rw & 31)) : (hp + rw);
            float4 wv = *(const float4*)(Wg + (size_t)orow * DIMM + kk + q4 * 4);
            *(float4*)&WS[rw * WSTR + q4 * 4] = wv;
        }
        __syncthreads();
#pragma unroll
        for (int k4 = 0; k4 < 8; k4++) {
            ulonglong2 b0 = *(const ulonglong2*)&WS[lane * WSTR + k4 * 4];
            ulonglong2 b1 = *(const ulonglong2*)&WS[(lane + 32) * WSTR + k4 * 4];
            ulonglong2 b2 = *(const ulonglong2*)&WS[(lane + 64) * WSTR + k4 * 4];
#pragma unroll
            for (int j = 0; j < 7; j++) {
                if (j < 6 || warp == 0) {
                    ulonglong2 a = *(const ulonglong2*)&A[(warp + 8 * j) * XSTR + kk + k4 * 4];
                    fma2(acc[j][0], a.x, b0.x); fma2(acc[j][0], a.y, b0.y);
                    fma2(acc[j][1], a.x, b1.x); fma2(acc[j][1], a.y, b1.y);
                    fma2(acc[j][2], a.x, b2.x); fma2(acc[j][2], a.y, b2.y);
                }
            }
        }
    }
#pragma unroll
    for (int j = 0; j < 7; j++)
#pragma unroll
        for (int c = 0; c < 3; c++) fin[j][c] = unpack_add(acc[j][c]);
}

__global__ __launch_bounds__(256, 1)
void win_attn_kernel(const float* __restrict__ x,
                     const float* __restrict__ mask,
                     const float* __restrict__ tbl,
                     const float* __restrict__ qkv_w,
                     const float* __restrict__ qkv_b,
                     const float* __restrict__ proj_w,
                     const float* __restrict__ proj_b,
                     const int*   __restrict__ rpi,
                     float* __restrict__ out)
{
    extern __shared__ float sm[];
    float* XS = sm + OFF_XS;
    float* OS = sm + OFF_OS;
    float* WS = sm + OFF_WS;
    float* QS = sm + OFF_QS;
    float* KS = sm + OFF_KS;
    float* VS = sm + OFF_VS;
    float* PS = sm + OFF_PS;
    float* TB = sm + OFF_TB;
    float* MS = sm + OFF_MS;
    int*   IX = (int*)(sm + OFF_IX);

    const int tid  = threadIdx.x;
    const int lane = tid & 31;
    const int warp = tid >> 5;
    const int b    = blockIdx.x;
    const int wm   = b & (NWIN - 1);

    // load x tile (49x384) into padded smem, vectorized
    const float4* x4 = (const float4*)(x + (size_t)b * NTOK * DIMM);
    for (int i = tid; i < NTOK * (DIMM / 4); i += 256) {
        int r = i / 96, c4 = i - r * 96;
        *(float4*)&XS[r * XSTR + c4 * 4] = x4[i];
    }
    // rel-pos index, this window's mask slice, rel-pos table
    for (int i = tid; i < NTOK * NTOK; i += 256) {
        IX[i] = rpi[i];
        MS[i] = mask[(size_t)wm * NTOK * NTOK + i];
    }
    for (int i = tid; i < 169 * NH; i += 256) TB[i] = tbl[i];
    // (first __syncthreads inside gemm96 orders the above vs first use)

    const bool v2  = (lane + 32) < NTOK;   // lane's second attention column valid?
    const int  jc2 = v2 ? lane + 32 : 0;

    for (int h = 0; h < NH; h++) {
        // ---- QKV for this head: q,k,v = x @ Wh^T (+b), q pre-scaled ----
        float fin[7][3];
        gemm96<true>(XS, qkv_w, h, WS, fin, tid, lane, warp);
        float bq = qkv_b[h * HDM + lane];
        float bk = qkv_b[384 + h * HDM + lane];
        float bv = qkv_b[768 + h * HDM + lane];
#pragma unroll
        for (int j = 0; j < 7; j++) {
            if (j < 6 || warp == 0) {
                int r = warp + 8 * j;
                QS[r * QSTR + lane] = (fin[j][0] + bq) * SCALE;
                KS[r * QSTR + lane] = fin[j][1] + bk;
                VS[r * QSTR + lane] = fin[j][2] + bv;
            }
        }
        __syncthreads();

        // ---- attention: scores + bias + mask + softmax (warp per row set) ----
#pragma unroll
        for (int j = 0; j < 7; j++) {
            if (j == 6 && warp != 0) break;    // warp-uniform
            int r = warp + 8 * j;
            float s1 = 0.f, s2 = 0.f;
#pragma unroll
            for (int d = 0; d < HDM; d++) {
                float qv = QS[r * QSTR + d];
                s1 = fmaf(qv, KS[lane * QSTR + d], s1);
                s2 = fmaf(qv, KS[jc2 * QSTR + d], s2);
            }
            s1 += TB[IX[r * NTOK + lane] * NH + h] + MS[r * NTOK + lane];
            s2 = v2 ? (s2 + TB[IX[r * NTOK + jc2] * NH + h] + MS[r * NTOK + jc2])
                    : -1e30f;
            float mx = fmaxf(s1, s2);
#pragma unroll
            for (int o = 16; o > 0; o >>= 1)
                mx = fmaxf(mx, __shfl_xor_sync(0xffffffffu, mx, o));
            float e1 = __expf(s1 - mx);
            float e2 = v2 ? __expf(s2 - mx) : 0.f;
            float sum = e1 + e2;
#pragma unroll
            for (int o = 16; o > 0; o >>= 1)
                sum += __shfl_xor_sync(0xffffffffu, sum, o);
            float inv = 1.0f / sum;
            PS[r * PSTR + lane] = e1 * inv;
            if (v2) PS[r * PSTR + lane + 32] = e2 * inv;
        }
        __syncwarp();

        // ---- P @ V -> attn-out columns for this head ----
#pragma unroll
        for (int j = 0; j < 7; j++) {
            if (j == 6 && warp != 0) break;
            int r = warp + 8 * j;
            float o = 0.f;
#pragma unroll
            for (int jj = 0; jj < NTOK; jj++)
                o = fmaf(PS[r * PSTR + jj], VS[jj * QSTR + lane], o);
            OS[r * XSTR + h * HDM + lane] = o;
        }
        // next head's gemm96 leading __syncthreads covers all smem hazards
    }

    // ---- projection: out = OS @ proj_w^T + proj_b (4 col-tiles of 96) ----
    float* outb = out + (size_t)b * NTOK * DIMM;
    for (int c0 = 0; c0 < DIMM; c0 += 96) {
        float fin[7][3];
        gemm96<false>(OS, proj_w, c0, WS, fin, tid, lane, warp);
        float p0 = proj_b[c0 + lane];
        float p1 = proj_b[c0 + lane + 32];
        float p2 = proj_b[c0 + lane + 64];
#pragma unroll
        for (int j = 0; j < 7; j++) {
            if (j < 6 || warp == 0) {
                int r = warp + 8 * j;
                outb[r * DIMM + c0 + lane]      = fin[j][0] + p0;
                outb[r * DIMM + c0 + lane + 32] = fin[j][1] + p1;
                outb[r * DIMM + c0 + lane + 64] = fin[j][2] + p2;
            }
        }
    }
}

extern "C" void kernel_launch(void* const* d_in, const int* in_sizes, int n_in,
                              void* d_out, int out_size)
{
    const float* x      = (const float*)d_in[0];
    const float* mask   = (const float*)d_in[1];
    const float* tbl    = (const float*)d_in[2];
    const float* qkv_w  = (const float*)d_in[3];
    const float* qkv_b  = (const float*)d_in[4];
    const float* proj_w = (const float*)d_in[5];
    const float* proj_b = (const float*)d_in[6];
    const int*   rpi    = (const int*)d_in[7];
    float* out = (float*)d_out;

    int B = in_sizes[0] / (NTOK * DIMM);   // 8192
    size_t smem = (size_t)SMEM_FLOATS * sizeof(float);   // 222,836 B
    cudaFuncSetAttribute(win_attn_kernel,
                         cudaFuncAttributeMaxDynamicSharedMemorySize, (int)smem);
    win_attn_kernel<<<B, 256, smem>>>(x, mask, tbl, qkv_w, qkv_b,
                                      proj_w, proj_b, rpi, out);
}